// round 1
// baseline (speedup 1.0000x reference)
#include <cuda_runtime.h>

// B=8, L=512, K=512, M=N=P=D=64
#define BB 8
#define LL 512
#define KS 512

__device__ float g_vkc[BB * KS * 64];   // [b][k][n] = sum_p vk[b,k,p,n]*vexp[b,k,p]
__device__ float g_tmp[BB * LL * 64];   // [b][l][n] = sum_k softmax(scores)[l,k]*vkc[b,k,n]

// ---------------------------------------------------------------------------
// Kernel 1: vkc[b,k,n] = sum_p vk[b,k,p,n] * vexp[b,k,p]   (streams vk, 67MB)
// ---------------------------------------------------------------------------
__global__ void vkc_kernel(const float* __restrict__ vk,
                           const float* __restrict__ vexp) {
    int idx = blockIdx.x * 256 + threadIdx.x;      // 0 .. 262143
    int n  = idx & 63;
    int bk = idx >> 6;                              // b*512 + k
    const float* vkp = vk + (size_t)bk * 4096 + n;  // stride 64 over p
    const float* ve  = vexp + (size_t)bk * 64;
    float acc = 0.f;
#pragma unroll
    for (int p = 0; p < 64; ++p)
        acc = fmaf(vkp[p * 64], __ldg(ve + p), acc);
    g_vkc[idx] = acc;
}

// ---------------------------------------------------------------------------
// Kernel 2: per (b, 16 l-rows): scores -> softmax -> tmp = W @ vkc
//   smem layout (floats): kst[256*65] | S[16*512] | qT[64*16] | srow[16]
// ---------------------------------------------------------------------------
#define K2_SMEM_FLOATS (16640 + 8192 + 1024 + 16)
#define K2_SMEM_BYTES  (K2_SMEM_FLOATS * 4)

__global__ __launch_bounds__(256, 2)
void attn_kernel(const float* __restrict__ q,
                 const float* __restrict__ k,
                 const float* __restrict__ scale_p) {
    extern __shared__ float sm[];
    float* kst  = sm;                   // 256 rows x pitch 65 (scores) / 256x64 (vkc stage)
    float* S    = sm + 16640;           // 16 x 512
    float* qT   = sm + 16640 + 8192;    // 64 x 16 (transposed q tile)
    float* srow = qT + 1024;            // 16 inverse row sums

    const int tid = threadIdx.x;
    const int b   = blockIdx.x >> 5;
    const int l0  = (blockIdx.x & 31) << 4;
    const float* qb = q + ((size_t)b * LL + l0) * 64;
    const float* kb = k + (size_t)b * KS * 64;
    const float sc  = scale_p[0];

    // stage q tile transposed: qT[d][l]
#pragma unroll
    for (int j = 0; j < 4; ++j) {
        int f = tid + 256 * j;          // f = l*64 + d
        int l = f >> 6, d = f & 63;
        qT[d * 16 + l] = qb[f];
    }

    const int l_t  = tid & 3;           // 4 l's: 4*l_t .. 4*l_t+3
    const int kc_t = tid >> 2;          // 4 kc's: 4*kc_t .. 4*kc_t+3 (within 256-chunk)

    // ---- scores: S[l][kc] = sc * q[l]·k[kc], two 256-wide kc chunks ----
    for (int c = 0; c < 2; ++c) {
        const float* kcb = kb + (size_t)c * 256 * 64;
#pragma unroll 4
        for (int j = 0; j < 64; ++j) {
            int f = tid + 256 * j;      // f = kc*64 + d  (coalesced read)
            int kc = f >> 6, d = f & 63;
            kst[kc * 65 + d] = kcb[f];
        }
        __syncthreads();

        float acc[4][4];                // [j=kc][i=l]
#pragma unroll
        for (int j = 0; j < 4; ++j)
#pragma unroll
            for (int i = 0; i < 4; ++i) acc[j][i] = 0.f;

        const float* kr = kst + (4 * kc_t) * 65;
#pragma unroll 8
        for (int d = 0; d < 64; ++d) {
            float4 qv = *(const float4*)(qT + d * 16 + 4 * l_t);
            float k0 = kr[d];
            float k1 = kr[65 + d];
            float k2 = kr[130 + d];
            float k3 = kr[195 + d];
            acc[0][0] = fmaf(k0, qv.x, acc[0][0]);
            acc[0][1] = fmaf(k0, qv.y, acc[0][1]);
            acc[0][2] = fmaf(k0, qv.z, acc[0][2]);
            acc[0][3] = fmaf(k0, qv.w, acc[0][3]);
            acc[1][0] = fmaf(k1, qv.x, acc[1][0]);
            acc[1][1] = fmaf(k1, qv.y, acc[1][1]);
            acc[1][2] = fmaf(k1, qv.z, acc[1][2]);
            acc[1][3] = fmaf(k1, qv.w, acc[1][3]);
            acc[2][0] = fmaf(k2, qv.x, acc[2][0]);
            acc[2][1] = fmaf(k2, qv.y, acc[2][1]);
            acc[2][2] = fmaf(k2, qv.z, acc[2][2]);
            acc[2][3] = fmaf(k2, qv.w, acc[2][3]);
            acc[3][0] = fmaf(k3, qv.x, acc[3][0]);
            acc[3][1] = fmaf(k3, qv.y, acc[3][1]);
            acc[3][2] = fmaf(k3, qv.z, acc[3][2]);
            acc[3][3] = fmaf(k3, qv.w, acc[3][3]);
        }
#pragma unroll
        for (int i = 0; i < 4; ++i) {
            float4 v = make_float4(acc[0][i] * sc, acc[1][i] * sc,
                                   acc[2][i] * sc, acc[3][i] * sc);
            *(float4*)(S + (size_t)(4 * l_t + i) * 512 + c * 256 + 4 * kc_t) = v;
        }
        __syncthreads();
    }

    // ---- softmax over kc (unnormalized; keep 1/sum in srow) ----
    {
        const int w = tid >> 5, lane = tid & 31;
#pragma unroll
        for (int r = 0; r < 2; ++r) {
            int l = w * 2 + r;
            float* Sr = S + (size_t)l * 512;
            float m = -1e30f;
#pragma unroll
            for (int i = 0; i < 16; ++i) m = fmaxf(m, Sr[lane + 32 * i]);
#pragma unroll
            for (int o = 16; o > 0; o >>= 1)
                m = fmaxf(m, __shfl_xor_sync(0xffffffffu, m, o));
            float s = 0.f;
#pragma unroll
            for (int i = 0; i < 16; ++i) {
                float e = __expf(Sr[lane + 32 * i] - m);
                Sr[lane + 32 * i] = e;
                s += e;
            }
#pragma unroll
            for (int o = 16; o > 0; o >>= 1)
                s += __shfl_xor_sync(0xffffffffu, s, o);
            if (lane == 0) srow[l] = 1.f / s;
        }
    }
    __syncthreads();

    // ---- tmp[l][n] = sum_kc W[l][kc] * vkc[b][kc][n] ----
    const int l2 = tid >> 5;            // warp -> l pair {2*l2, 2*l2+1}
    const int n2 = (tid & 31) * 2;      // {n2, n2+1}
    float a00 = 0.f, a01 = 0.f, a10 = 0.f, a11 = 0.f;
    const float* W0 = S + (size_t)(2 * l2) * 512;
    const float* W1 = W0 + 512;
    const float* gv = g_vkc + (size_t)b * KS * 64;

    for (int c = 0; c < 2; ++c) {
#pragma unroll 4
        for (int j = 0; j < 16; ++j) {  // copy 256x64 floats = 4096 float4
            int f4 = tid + 256 * j;
            ((float4*)kst)[f4] = ((const float4*)(gv + (size_t)c * 16384))[f4];
        }
        __syncthreads();
#pragma unroll 4
        for (int kk = 0; kk < 256; ++kk) {
            int kc = c * 256 + kk;
            float w0 = W0[kc], w1 = W1[kc];
            float2 v = *(const float2*)(kst + kk * 64 + n2);
            a00 = fmaf(w0, v.x, a00);
            a01 = fmaf(w0, v.y, a01);
            a10 = fmaf(w1, v.x, a10);
            a11 = fmaf(w1, v.y, a11);
        }
        __syncthreads();
    }
    float i0 = srow[2 * l2], i1 = srow[2 * l2 + 1];
    float* tp = g_tmp + ((size_t)b * LL + l0) * 64;
    *(float2*)(tp + (size_t)(2 * l2) * 64 + n2)     = make_float2(a00 * i0, a01 * i0);
    *(float2*)(tp + (size_t)(2 * l2 + 1) * 64 + n2) = make_float2(a10 * i1, a11 * i1);
}

// ---------------------------------------------------------------------------
// Kernel 3: per (b,l): attn[m] = vq[l]·tmp[l]; out = LayerNorm(q + attn)
//   streams vq (67MB)
// ---------------------------------------------------------------------------
__global__ __launch_bounds__(256)
void out_kernel(const float* __restrict__ q,
                const float* __restrict__ vq,
                const float* __restrict__ gamma,
                const float* __restrict__ beta,
                float* __restrict__ out) {
    __shared__ float svq[64 * 65];
    __shared__ float stmp[64];
    __shared__ float sq[64];
    __shared__ float red[4];

    const int tid = threadIdx.x;
    const int bl  = blockIdx.x;         // b*512 + l
    const float* vqp = vq + (size_t)bl * 4096;

#pragma unroll
    for (int j = 0; j < 4; ++j) {       // coalesced float4 -> padded smem
        int f4 = tid + 256 * j;
        float4 v = ((const float4*)vqp)[f4];
        int m  = f4 >> 4;
        int n0 = (f4 & 15) * 4;
        float* dst = svq + m * 65 + n0;
        dst[0] = v.x; dst[1] = v.y; dst[2] = v.z; dst[3] = v.w;
    }
    if (tid < 64) {
        stmp[tid] = g_tmp[(size_t)bl * 64 + tid];
        sq[tid]   = q[(size_t)bl * 64 + tid];
    }
    __syncthreads();

    float y = 0.f;
    if (tid < 64) {
        float acc = 0.f;
#pragma unroll 8
        for (int n = 0; n < 64; ++n)
            acc = fmaf(svq[tid * 65 + n], stmp[n], acc);
        y = sq[tid] + acc;
        float s1 = y;
#pragma unroll
        for (int o = 16; o > 0; o >>= 1)
            s1 += __shfl_xor_sync(0xffffffffu, s1, o);
        if ((tid & 31) == 0) red[tid >> 5] = s1;
    }
    __syncthreads();
    float mu = (red[0] + red[1]) * (1.f / 64.f);
    if (tid < 64) {
        float d = y - mu;
        float s2 = d * d;
#pragma unroll
        for (int o = 16; o > 0; o >>= 1)
            s2 += __shfl_xor_sync(0xffffffffu, s2, o);
        if ((tid & 31) == 0) red[2 + (tid >> 5)] = s2;
    }
    __syncthreads();
    if (tid < 64) {
        float var = (red[2] + red[3]) * (1.f / 64.f);
        float r = rsqrtf(var + 1e-3f);  // keras eps per reference
        out[(size_t)bl * 64 + tid] =
            (y - mu) * r * __ldg(gamma + tid) + __ldg(beta + tid);
    }
}

// ---------------------------------------------------------------------------
extern "C" void kernel_launch(void* const* d_in, const int* in_sizes, int n_in,
                              void* d_out, int out_size) {
    (void)in_sizes; (void)n_in; (void)out_size;
    const float* q     = (const float*)d_in[0];
    const float* k     = (const float*)d_in[1];
    const float* vq    = (const float*)d_in[2];
    const float* vk    = (const float*)d_in[3];
    const float* vexp  = (const float*)d_in[4];
    const float* scale = (const float*)d_in[5];
    const float* gamma = (const float*)d_in[6];
    const float* beta  = (const float*)d_in[7];
    float* out = (float*)d_out;

    cudaFuncSetAttribute(attn_kernel,
                         cudaFuncAttributeMaxDynamicSharedMemorySize,
                         K2_SMEM_BYTES);

    vkc_kernel<<<BB * KS * 64 / 256, 256>>>(vk, vexp);
    attn_kernel<<<BB * (LL / 16), 256, K2_SMEM_BYTES>>>(q, k, scale);
    out_kernel<<<BB * LL, 256>>>(q, vq, gamma, beta, out);
}